// round 13
// baseline (speedup 1.0000x reference)
#include <cuda_runtime.h>
#include <cuda_bf16.h>

// out[b,d,n] = w[d] * in[b,d,n];  B=8, D=2048, N=2048, fp32.
// FINAL: HBM-bound stream at the B300 R/W-mix DRAM ceiling. Evidence across
// 9 measured rounds: seven structural variants (MLP 1/4/8, .cs hints, 256-bit
// ld/st, TMA bulk store, 1/2/7-wave tilings) all land 69-76% DRAM; the
// identical binary measured 35.6us and 39.2us in different container
// sessions, so that whole band is cross-session clock/thermal noise.
// Byte count (268MB fp32, zero reuse, output dtype fixed) bounds the kernel
// at ~34us ideal. This config: front-batched 4x independent LDG.128 per
// thread, plain STG.128, exact-cover grid, weights (8KB) L2-resident.
// Best recorded: 35.65us kernel / 43.49us wall.

static constexpr int B = 8;
static constexpr int D = 2048;
static constexpr int N = 2048;
static constexpr long long TOTAL4 = (long long)B * D * N / 4;  // 8,388,608 float4
static constexpr int THREADS = 256;
static constexpr int UNROLL  = 4;
static constexpr int BLOCK_ELEMS = THREADS * UNROLL;           // 1024 float4 / block

__global__ void __launch_bounds__(THREADS)
channel_scale_kernel(const float4* __restrict__ in,
                     const float*  __restrict__ w,
                     float4*       __restrict__ out)
{
    long long base = (long long)blockIdx.x * BLOCK_ELEMS + threadIdx.x;

    // Front-batch all loads: 4 independent LDG.128 in flight per thread.
    float4 v[UNROLL];
#pragma unroll
    for (int k = 0; k < UNROLL; k++) {
        v[k] = in[base + (long long)k * THREADS];
    }

#pragma unroll
    for (int k = 0; k < UNROLL; k++) {
        long long i = base + (long long)k * THREADS;
        // channel index: i4 / (N/4) % D ; N/4 = 512, D = 2048
        int d = (int)((i >> 9) & (D - 1));
        float s = __ldg(w + d);          // L1/L2 resident (8 KB)
        v[k].x *= s; v[k].y *= s; v[k].z *= s; v[k].w *= s;
        out[i] = v[k];
    }
}

extern "C" void kernel_launch(void* const* d_in, const int* in_sizes, int n_in,
                              void* d_out, int out_size)
{
    const float4* in = (const float4*)d_in[0];   // inputs [B, D, N] fp32
    const float*  w  = (const float*)d_in[1];    // attention_weights [D] fp32
    float4* out = (float4*)d_out;

    long long blocks = TOTAL4 / BLOCK_ELEMS;     // 8192, exact cover
    channel_scale_kernel<<<(unsigned)blocks, THREADS>>>(in, w, out);
}

// round 14
// speedup vs baseline: 1.0085x; 1.0085x over previous
#include <cuda_runtime.h>
#include <cuda_bf16.h>

// out[b,d,n] = w[d] * in[b,d,n];  B=8, D=2048, N=2048, fp32.
// R14: plain-access UNROLL=8 (the one untested cell: R3 ran unroll=8 only
// with .cs hints). 8 front-batched independent LDG.128 per thread to hide
// the longer effective DRAM latency seen in this session's lower-clock state
// (L1 queue pressure 40%->66% vs the fast session). Exact-cover grid,
// weights (8KB) L2-resident via __ldg.

static constexpr int B = 8;
static constexpr int D = 2048;
static constexpr int N = 2048;
static constexpr long long TOTAL4 = (long long)B * D * N / 4;  // 8,388,608 float4
static constexpr int THREADS = 256;
static constexpr int UNROLL  = 8;
static constexpr int BLOCK_ELEMS = THREADS * UNROLL;           // 2048 float4 / block

__global__ void __launch_bounds__(THREADS)
channel_scale_kernel(const float4* __restrict__ in,
                     const float*  __restrict__ w,
                     float4*       __restrict__ out)
{
    long long base = (long long)blockIdx.x * BLOCK_ELEMS + threadIdx.x;

    // Front-batch all loads: 8 independent LDG.128 in flight per thread.
    float4 v[UNROLL];
#pragma unroll
    for (int k = 0; k < UNROLL; k++) {
        v[k] = in[base + (long long)k * THREADS];
    }

#pragma unroll
    for (int k = 0; k < UNROLL; k++) {
        long long i = base + (long long)k * THREADS;
        // channel index: i4 / (N/4) % D ; N/4 = 512, D = 2048
        int d = (int)((i >> 9) & (D - 1));
        float s = __ldg(w + d);          // L1/L2 resident (8 KB)
        v[k].x *= s; v[k].y *= s; v[k].z *= s; v[k].w *= s;
        out[i] = v[k];
    }
}

extern "C" void kernel_launch(void* const* d_in, const int* in_sizes, int n_in,
                              void* d_out, int out_size)
{
    const float4* in = (const float4*)d_in[0];   // inputs [B, D, N] fp32
    const float*  w  = (const float*)d_in[1];    // attention_weights [D] fp32
    float4* out = (float4*)d_out;

    long long blocks = TOTAL4 / BLOCK_ELEMS;     // 4096, exact cover
    channel_scale_kernel<<<(unsigned)blocks, THREADS>>>(in, w, out);
}